// round 12
// baseline (speedup 1.0000x reference)
#include <cuda_runtime.h>
#include <cstdint>

#define S 2048
#define B 32
#define I 256
#define H 256
#define G4 1024
#define NCTA 128
#define NTHR2 512
#define CLUS 16   // CTAs per cluster (= per batch group)

// Static device scratch (no cudaMalloc allowed).
__device__ float g_Wp[I * G4];                 // packed input weights  [k][colp]
__device__ float g_Up[H * G4];                 // packed recurrent wts  [k][colp]
__device__ float g_bp[G4];                     // packed bias
__device__ float g_xg[(size_t)S * B * G4];     // input projections [t][cta][bq][64]

// colp mapping: gate = colp&3 (0=f,1=i,2=c,3=o), jl = (colp>>2)&15, l = colp>>6
// hidden dim j = l*16 + jl. CTA (g,l) owns batches 4g..4g+3 and cols l*64..l*64+63.
__global__ void pack_kernel(
    const float* __restrict__ Wf, const float* __restrict__ Wi,
    const float* __restrict__ Wc, const float* __restrict__ Wo,
    const float* __restrict__ Uf, const float* __restrict__ Ui,
    const float* __restrict__ Uc, const float* __restrict__ Uo,
    const float* __restrict__ bf, const float* __restrict__ bi,
    const float* __restrict__ bc, const float* __restrict__ bo)
{
    int idx = blockIdx.x * blockDim.x + threadIdx.x;
    if (idx < I * G4) {
        int k    = idx >> 10;
        int colp = idx & 1023;
        int g    = colp & 3;
        int jl   = (colp >> 2) & 15;
        int l    = colp >> 6;
        int j    = l * 16 + jl;
        const float* W = (g == 0) ? Wf : (g == 1) ? Wi : (g == 2) ? Wc : Wo;
        const float* U = (g == 0) ? Uf : (g == 1) ? Ui : (g == 2) ? Uc : Uo;
        g_Wp[idx] = W[k * H + j];
        g_Up[idx] = U[k * H + j];
        if (k == 0) {
            const float* bv = (g == 0) ? bf : (g == 1) ? bi : (g == 2) ? bc : bo;
            g_bp[colp] = bv[j];
        }
    }
}

// ---------------- Phase 1: xg = x @ Wp + bp, output [t][cta][bq][64] ----------------
#define BM 64
#define BN 64
#define BK 16

__global__ __launch_bounds__(256) void gemm_xg_kernel(const float* __restrict__ x)
{
    __shared__ float As[BK][BM + 4];
    __shared__ float Bs[BK][BN];

    int tid = threadIdx.x;
    int r0 = blockIdx.y * BM;   // rows r = t*B + b
    int c0 = blockIdx.x * BN;
    int tr = tid >> 4, tc = tid & 15;

    int aRow = tid >> 2;
    int aK   = (tid & 3) << 2;
    int bK   = tid >> 4;
    int bC   = (tid & 15) << 2;

    int r  = r0 + aRow;
    int bb = r & 31;
    int tt = r >> 5;
    const float* aptr = x + ((size_t)bb * S + tt) * I + aK;

    float acc[4][4];
#pragma unroll
    for (int i2 = 0; i2 < 4; ++i2)
#pragma unroll
        for (int j2 = 0; j2 < 4; ++j2) acc[i2][j2] = 0.f;

    for (int k0 = 0; k0 < I; k0 += BK) {
        float4 av = *(const float4*)(aptr + k0);
        As[aK + 0][aRow] = av.x;
        As[aK + 1][aRow] = av.y;
        As[aK + 2][aRow] = av.z;
        As[aK + 3][aRow] = av.w;
        float4 bv = *(const float4*)(g_Wp + (size_t)(k0 + bK) * G4 + c0 + bC);
        *(float4*)&Bs[bK][bC] = bv;
        __syncthreads();
#pragma unroll
        for (int kk = 0; kk < BK; ++kk) {
            float4 a4 = *(const float4*)&As[kk][tr << 2];
            float4 b4 = *(const float4*)&Bs[kk][tc << 2];
            acc[0][0] = fmaf(a4.x, b4.x, acc[0][0]);
            acc[0][1] = fmaf(a4.x, b4.y, acc[0][1]);
            acc[0][2] = fmaf(a4.x, b4.z, acc[0][2]);
            acc[0][3] = fmaf(a4.x, b4.w, acc[0][3]);
            acc[1][0] = fmaf(a4.y, b4.x, acc[1][0]);
            acc[1][1] = fmaf(a4.y, b4.y, acc[1][1]);
            acc[1][2] = fmaf(a4.y, b4.z, acc[1][2]);
            acc[1][3] = fmaf(a4.y, b4.w, acc[1][3]);
            acc[2][0] = fmaf(a4.z, b4.x, acc[2][0]);
            acc[2][1] = fmaf(a4.z, b4.y, acc[2][1]);
            acc[2][2] = fmaf(a4.z, b4.z, acc[2][2]);
            acc[2][3] = fmaf(a4.z, b4.w, acc[2][3]);
            acc[3][0] = fmaf(a4.w, b4.x, acc[3][0]);
            acc[3][1] = fmaf(a4.w, b4.y, acc[3][1]);
            acc[3][2] = fmaf(a4.w, b4.z, acc[3][2]);
            acc[3][3] = fmaf(a4.w, b4.w, acc[3][3]);
        }
        __syncthreads();
    }

    int col = c0 + (tc << 2);         // global packed col, 4-aligned
    int l   = col >> 6;
    int c63 = col & 63;               // stays within 64-block for the float4
    float4 bias = *(const float4*)&g_bp[col];
#pragma unroll
    for (int i2 = 0; i2 < 4; ++i2) {
        int rr  = r0 + (tr << 2) + i2;
        int tt2 = rr >> 5;
        int bb2 = rr & 31;
        int grp = bb2 >> 2;
        int bq  = bb2 & 3;
        float4 o;
        o.x = acc[i2][0] + bias.x;
        o.y = acc[i2][1] + bias.y;
        o.z = acc[i2][2] + bias.z;
        o.w = acc[i2][3] + bias.w;
        *(float4*)(g_xg + (((size_t)tt2 * NCTA + grp * CLUS + l) * 4 + bq) * 64 + c63) = o;
    }
}

// ---------------- Phase 2: persistent recurrence with cluster DSMEM ----------------
__device__ __forceinline__ float sig_(float v) {
    return __fdividef(1.f, 1.f + __expf(-v));
}
__device__ __forceinline__ float tanh_(float v) {
    return 1.f - __fdividef(2.f, 1.f + __expf(2.f * v));
}

__device__ __forceinline__ uint32_t smem_u32(const void* p) {
    uint32_t a;
    asm("{ .reg .u64 t; cvta.to.shared.u64 t, %1; cvt.u32.u64 %0, t; }"
        : "=r"(a) : "l"(p));
    return a;
}

__global__ __launch_bounds__(NTHR2, 1) void lstm_kernel(float* __restrict__ out, int out_size)
{
    __shared__ __align__(16) float h_s[2][4][256];   // ping-pong h [slot][bq][dim]
    __shared__ float xs[64][4];                      // staged xg [col64][bq]
    __shared__ float z_s[16][4][4];                  // [dimw][gate][bq]
    __shared__ __align__(16) float hstage[4][16];    // this CTA's new h [bq][dimw]
    __shared__ __align__(8) unsigned long long mbar;

    int cta  = blockIdx.x;
    int g    = cta >> 4;              // batch group / cluster id
    int l    = cta & 15;              // rank within cluster
    int tid  = threadIdx.x;
    int lane = tid & 31;
    int w    = tid >> 5;              // warp -> local dim w, gate cols w*4..w*4+3

    uint32_t mbar_a = smem_u32(&mbar);

    // zero both h slots (h_{-1} = 0)
    for (int i = tid; i < 2 * 4 * 256; i += NTHR2)
        ((float*)h_s)[i] = 0.f;
    if (tid == 0) {
        asm volatile("mbarrier.init.shared.b64 [%0], %1;" :: "r"(mbar_a), "r"(CLUS) : "memory");
    }

    // hoist U into registers (time-invariant), same as R8
    unsigned long long u2[2][2][4];
#pragma unroll
    for (int iq = 0; iq < 2; ++iq)
#pragma unroll
        for (int pp = 0; pp < 2; ++pp)
#pragma unroll
            for (int cc = 0; cc < 4; ++cc) {
                int col = l * 64 + w * 4 + cc;
                int k   = (iq * 32 + lane) * 4 + pp * 2;
                unsigned lo = __float_as_uint(g_Up[(size_t)k * G4 + col]);
                unsigned hi = __float_as_uint(g_Up[(size_t)(k + 1) * G4 + col]);
                u2[iq][pp][cc] = ((unsigned long long)hi << 32) | lo;
            }

    int dimw = tid >> 2;              // gate threads (tid<64)
    int bq_g = tid & 3;
    float cstate = 0.f;

    // xg prefetch threads (tid<64): bq = tid>>4, col offset = (tid&15)*4
    int pbq = tid >> 4;
    int pc  = (tid & 15) * 4;
    float4 xv = make_float4(0.f, 0.f, 0.f, 0.f);
    if (tid < 64)
        xv = __ldg((const float4*)(g_xg + (((size_t)0 * NCTA + cta) * 4 + pbq) * 64 + pc));

    __syncthreads();
    // cluster barrier: mbarriers + h slots initialized in ALL CTAs before any peer traffic
    asm volatile("barrier.cluster.arrive.aligned;" ::: "memory");
    asm volatile("barrier.cluster.wait.aligned;" ::: "memory");

    for (int t = 0; t < S; ++t) {
        // park this step's xg and issue next step's prefetch BEFORE the wait
        // (overlaps the LDG with the mbarrier wait shadow)
        if (tid < 64) {
            xs[pc + 0][pbq] = xv.x;
            xs[pc + 1][pbq] = xv.y;
            xs[pc + 2][pbq] = xv.z;
            xs[pc + 3][pbq] = xv.w;
            if (t + 1 < S)
                xv = __ldg((const float4*)(g_xg + (((size_t)(t + 1) * NCTA + cta) * 4 + pbq) * 64 + pc));
        }

        // wait for all 16 producers' step-(t-1) h: ONE waiter, others park at bar
        if (t > 0) {
            if (tid == 0) {
                unsigned parity = (unsigned)((t - 1) & 1);
                asm volatile(
                    "{\n\t"
                    ".reg .pred P;\n\t"
                    "W%=:\n\t"
                    "mbarrier.try_wait.parity.acquire.cluster.shared::cta.b64 P, [%0], %1, 0x989680;\n\t"
                    "@P bra D%=;\n\t"
                    "bra W%=;\n\t"
                    "D%=:\n\t"
                    "}"
                    :: "r"(mbar_a), "r"(parity) : "memory");
            }
            __syncthreads();
        }

        // read h_{t-1} from LOCAL smem slot (t-1)&1 == (t+1)&1
        const float* hs = &h_s[(t + 1) & 1][0][0];
        float4 hq[2][4];
#pragma unroll
        for (int iq = 0; iq < 2; ++iq)
#pragma unroll
            for (int bq = 0; bq < 4; ++bq)
                hq[iq][bq] = *(const float4*)(hs + bq * 256 + (iq * 32 + lane) * 4);

        unsigned long long acc[4][4];   // [cc][bq]
#pragma unroll
        for (int cc = 0; cc < 4; ++cc)
#pragma unroll
            for (int bq = 0; bq < 4; ++bq) acc[cc][bq] = 0ull;

#pragma unroll
        for (int iq = 0; iq < 2; ++iq)
#pragma unroll
            for (int bq = 0; bq < 4; ++bq) {
                unsigned long long hx =
                    ((unsigned long long)__float_as_uint(hq[iq][bq].y) << 32) | __float_as_uint(hq[iq][bq].x);
                unsigned long long hy =
                    ((unsigned long long)__float_as_uint(hq[iq][bq].w) << 32) | __float_as_uint(hq[iq][bq].z);
#pragma unroll
                for (int cc = 0; cc < 4; ++cc) {
                    asm("fma.rn.f32x2 %0, %1, %2, %0;"
                        : "+l"(acc[cc][bq]) : "l"(u2[iq][0][cc]), "l"(hx));
                    asm("fma.rn.f32x2 %0, %1, %2, %0;"
                        : "+l"(acc[cc][bq]) : "l"(u2[iq][1][cc]), "l"(hy));
                }
            }

        // horizontal pair add -> v[m], m = cc*4+bq
        float v[16];
#pragma unroll
        for (int cc = 0; cc < 4; ++cc)
#pragma unroll
            for (int bq = 0; bq < 4; ++bq) {
                unsigned long long a = acc[cc][bq];
                v[cc * 4 + bq] =
                    __uint_as_float((unsigned)a) + __uint_as_float((unsigned)(a >> 32));
            }

        // warp butterfly reduction over 32 lanes (k-slices), 16 outputs
        {
            bool h4 = (lane & 16) != 0;
#pragma unroll
            for (int m = 0; m < 8; ++m) {
                float send = h4 ? v[m] : v[m + 8];
                float recv = __shfl_xor_sync(0xffffffffu, send, 16);
                v[m] = (h4 ? v[m + 8] : v[m]) + recv;
            }
            bool h3 = (lane & 8) != 0;
#pragma unroll
            for (int m = 0; m < 4; ++m) {
                float send = h3 ? v[m] : v[m + 4];
                float recv = __shfl_xor_sync(0xffffffffu, send, 8);
                v[m] = (h3 ? v[m + 4] : v[m]) + recv;
            }
            bool h2b = (lane & 4) != 0;
#pragma unroll
            for (int m = 0; m < 2; ++m) {
                float send = h2b ? v[m] : v[m + 2];
                float recv = __shfl_xor_sync(0xffffffffu, send, 4);
                v[m] = (h2b ? v[m + 2] : v[m]) + recv;
            }
            bool h1 = (lane & 2) != 0;
            {
                float send = h1 ? v[0] : v[1];
                float recv = __shfl_xor_sync(0xffffffffu, send, 2);
                v[0] = (h1 ? v[1] : v[0]) + recv;
            }
            v[0] += __shfl_xor_sync(0xffffffffu, v[0], 1);
        }
        if ((lane & 1) == 0) {
            int m = ((lane >> 4) & 1) * 8 + ((lane >> 3) & 1) * 4 +
                    ((lane >> 2) & 1) * 2 + ((lane >> 1) & 1);
            z_s[w][m >> 2][m & 3] = v[0];
        }
        __syncthreads();

        float hh = 0.f;
        if (tid < 64) {
            float zf = z_s[dimw][0][bq_g] + xs[dimw * 4 + 0][bq_g];
            float zi = z_s[dimw][1][bq_g] + xs[dimw * 4 + 1][bq_g];
            float zc = z_s[dimw][2][bq_g] + xs[dimw * 4 + 2][bq_g];
            float zo = z_s[dimw][3][bq_g] + xs[dimw * 4 + 3][bq_g];
            float f  = sig_(zf);
            float ii = sig_(zi);
            float gg = tanh_(zc);
            float oo = sig_(zo);
            cstate = fmaf(f, cstate, ii * gg);
            hh = oo * tanh_(cstate);
            hstage[bq_g][dimw] = hh;
        }
        __syncthreads();

        // push our 16 dims x 4 batches of h_t into ALL 16 peers' smem slot t&1
        if (tid < 256) {
            int peer = tid >> 4;
            int b    = (tid >> 2) & 3;
            int f4   = tid & 3;
            float4 val = *(const float4*)&hstage[b][f4 * 4];
            uint32_t laddr = smem_u32(&h_s[t & 1][b][l * 16 + f4 * 4]);
            uint32_t raddr;
            asm("mapa.shared::cluster.u32 %0, %1, %2;" : "=r"(raddr) : "r"(laddr), "r"(peer));
            asm volatile("st.shared::cluster.v4.f32 [%0], {%1,%2,%3,%4};"
                         :: "r"(raddr), "f"(val.x), "f"(val.y), "f"(val.z), "f"(val.w)
                         : "memory");
        }
        __syncthreads();   // all our DSMEM stores issued before the release-arrive

        if (tid < CLUS) {
            uint32_t raddr;
            asm("mapa.shared::cluster.u32 %0, %1, %2;" : "=r"(raddr) : "r"(mbar_a), "r"(tid));
            asm volatile("mbarrier.arrive.release.cluster.shared::cluster.b64 _, [%0];"
                         :: "r"(raddr) : "memory");
        }

        // off-critical-path output stores
        if (tid < 64) {
            int b   = g * 4 + bq_g;
            int dim = l * 16 + dimw;
            out[(size_t)b * (S * H) + (size_t)t * H + dim] = hh;
            if (t == S - 1) {
                size_t base = (size_t)B * S * H;
                if ((size_t)out_size >= base + 2 * (size_t)B * H) {
                    out[base + (size_t)b * H + dim] = hh;
                    out[base + (size_t)B * H + (size_t)b * H + dim] = cstate;
                }
            }
        }
    }

    // keep smem alive until all peers' in-flight DSMEM traffic is done
    asm volatile("barrier.cluster.arrive.aligned;" ::: "memory");
    asm volatile("barrier.cluster.wait.aligned;" ::: "memory");
}

extern "C" void kernel_launch(void* const* d_in, const int* in_sizes, int n_in,
                              void* d_out, int out_size) {
    (void)in_sizes; (void)n_in;
    const float* x  = (const float*)d_in[0];
    const float* Wf = (const float*)d_in[1];
    const float* Uf = (const float*)d_in[2];
    const float* bf = (const float*)d_in[3];
    const float* Wi = (const float*)d_in[4];
    const float* Ui = (const float*)d_in[5];
    const float* bi = (const float*)d_in[6];
    const float* Wo = (const float*)d_in[7];
    const float* Uo = (const float*)d_in[8];
    const float* bo = (const float*)d_in[9];
    const float* Wc = (const float*)d_in[10];
    const float* Uc = (const float*)d_in[11];
    const float* bc = (const float*)d_in[12];

    pack_kernel<<<1024, 256>>>(Wf, Wi, Wc, Wo, Uf, Ui, Uc, Uo, bf, bi, bc, bo);
    gemm_xg_kernel<<<dim3(G4 / BN, (S * B) / BM), 256>>>(x);

    static int attr_done = 0;
    if (!attr_done) {
        cudaFuncSetAttribute(lstm_kernel,
                             cudaFuncAttributeNonPortableClusterSizeAllowed, 1);
        attr_done = 1;
    }
    cudaLaunchConfig_t cfg = {};
    cfg.gridDim  = dim3(NCTA, 1, 1);
    cfg.blockDim = dim3(NTHR2, 1, 1);
    cfg.dynamicSmemBytes = 0;
    cfg.stream = 0;
    cudaLaunchAttribute attrs[1];
    attrs[0].id = cudaLaunchAttributeClusterDimension;
    attrs[0].val.clusterDim.x = CLUS;
    attrs[0].val.clusterDim.y = 1;
    attrs[0].val.clusterDim.z = 1;
    cfg.attrs = attrs;
    cfg.numAttrs = 1;
    cudaLaunchKernelEx(&cfg, lstm_kernel, (float*)d_out, out_size);
}

// round 13
// speedup vs baseline: 1.5954x; 1.5954x over previous
#include <cuda_runtime.h>
#include <cstdint>

#define S 2048
#define B 32
#define I 256
#define H 256
#define G4 1024
#define NCTA 128
#define NTHR2 512
#define GD 16     // CTAs per group
#define SENT 0x7FC000AAu   // NaN sentinel (gates can never produce NaN)

// Static device scratch (no cudaMalloc allowed).
__device__ float g_Wp[I * G4];                 // packed input weights  [k][colp]
__device__ float g_Up[H * G4];                 // packed recurrent wts  [k][colp]
__device__ float g_bp[G4];                     // packed bias
__device__ float g_xg[(size_t)S * B * G4];     // input projections [t][cta][bq][64]
__device__ float g_hseq[(size_t)(S + 1) * B * H];  // h history [t][b][dim]; slot 0 = zeros

// colp mapping: gate = colp&3 (0=f,1=i,2=c,3=o), jl = (colp>>2)&15, l = colp>>6
// hidden dim j = l*16 + jl. CTA (g,l) owns batches 4g..4g+3 and cols l*64..l*64+63.
__global__ void pack_kernel(
    const float* __restrict__ Wf, const float* __restrict__ Wi,
    const float* __restrict__ Wc, const float* __restrict__ Wo,
    const float* __restrict__ Uf, const float* __restrict__ Ui,
    const float* __restrict__ Uc, const float* __restrict__ Uo,
    const float* __restrict__ bf, const float* __restrict__ bi,
    const float* __restrict__ bc, const float* __restrict__ bo)
{
    int idx = blockIdx.x * blockDim.x + threadIdx.x;
    if (idx < I * G4) {
        int k    = idx >> 10;
        int colp = idx & 1023;
        int g    = colp & 3;
        int jl   = (colp >> 2) & 15;
        int l    = colp >> 6;
        int j    = l * 16 + jl;
        const float* W = (g == 0) ? Wf : (g == 1) ? Wi : (g == 2) ? Wc : Wo;
        const float* U = (g == 0) ? Uf : (g == 1) ? Ui : (g == 2) ? Uc : Uo;
        g_Wp[idx] = W[k * H + j];
        g_Up[idx] = U[k * H + j];
        if (k == 0) {
            const float* bv = (g == 0) ? bf : (g == 1) ? bi : (g == 2) ? bc : bo;
            g_bp[colp] = bv[j];
        }
    }
}

// Prefill h history: slot 0 = zeros (h_{-1}), slots 1..S = sentinel NaN.
__global__ void hinit_kernel()
{
    size_t tot = (size_t)(S + 1) * B * H;
    size_t stride = (size_t)gridDim.x * blockDim.x;
    float sent = __uint_as_float(SENT);
    for (size_t i = (size_t)blockIdx.x * blockDim.x + threadIdx.x; i < tot; i += stride)
        g_hseq[i] = (i < (size_t)B * H) ? 0.f : sent;
}

// ---------------- Phase 1: xg = x @ Wp + bp, output [t][cta][bq][64] ----------------
#define BM 128
#define BN 64
#define BK 16

__global__ __launch_bounds__(256) void gemm_xg_kernel(const float* __restrict__ x)
{
    __shared__ float As[BK][BM + 4];   // transposed A tile
    __shared__ float Bs[BK][BN];

    int tid = threadIdx.x;
    int r0 = blockIdx.y * BM;   // rows r = t*B + b
    int c0 = blockIdx.x * BN;
    int tr = tid >> 4;          // 0..15 -> rows tr*8..+7
    int tc = tid & 15;          // 0..15 -> cols tc*4..+3

    int aRow = tid >> 1;              // 0..127
    int aK   = (tid & 1) * 8;         // 0 or 8
    int bK   = tid >> 4;              // 0..15
    int bC   = (tid & 15) << 2;       // 0..60

    int r  = r0 + aRow;
    int bb = r & 31;
    int tt = r >> 5;
    const float* aptr = x + ((size_t)bb * S + tt) * I + aK;

    float acc[8][4];
#pragma unroll
    for (int i2 = 0; i2 < 8; ++i2)
#pragma unroll
        for (int j2 = 0; j2 < 4; ++j2) acc[i2][j2] = 0.f;

    for (int k0 = 0; k0 < I; k0 += BK) {
        float4 a1 = *(const float4*)(aptr + k0);
        float4 a2 = *(const float4*)(aptr + k0 + 4);
        As[aK + 0][aRow] = a1.x;
        As[aK + 1][aRow] = a1.y;
        As[aK + 2][aRow] = a1.z;
        As[aK + 3][aRow] = a1.w;
        As[aK + 4][aRow] = a2.x;
        As[aK + 5][aRow] = a2.y;
        As[aK + 6][aRow] = a2.z;
        As[aK + 7][aRow] = a2.w;
        float4 bv = *(const float4*)(g_Wp + (size_t)(k0 + bK) * G4 + c0 + bC);
        *(float4*)&Bs[bK][bC] = bv;
        __syncthreads();
#pragma unroll
        for (int kk = 0; kk < BK; ++kk) {
            float4 b4 = *(const float4*)&Bs[kk][tc << 2];
            float4 a4lo = *(const float4*)&As[kk][tr << 3];
            float4 a4hi = *(const float4*)&As[kk][(tr << 3) + 4];
            float av[8] = {a4lo.x, a4lo.y, a4lo.z, a4lo.w, a4hi.x, a4hi.y, a4hi.z, a4hi.w};
#pragma unroll
            for (int i2 = 0; i2 < 8; ++i2) {
                acc[i2][0] = fmaf(av[i2], b4.x, acc[i2][0]);
                acc[i2][1] = fmaf(av[i2], b4.y, acc[i2][1]);
                acc[i2][2] = fmaf(av[i2], b4.z, acc[i2][2]);
                acc[i2][3] = fmaf(av[i2], b4.w, acc[i2][3]);
            }
        }
        __syncthreads();
    }

    int col = c0 + (tc << 2);         // global packed col, 4-aligned
    int l   = col >> 6;
    int c63 = col & 63;               // stays within 64-block for the float4
    float4 bias = *(const float4*)&g_bp[col];
#pragma unroll
    for (int i2 = 0; i2 < 8; ++i2) {
        int rr  = r0 + (tr << 3) + i2;
        int tt2 = rr >> 5;
        int bb2 = rr & 31;
        int grp = bb2 >> 2;
        int bq  = bb2 & 3;
        float4 o;
        o.x = acc[i2][0] + bias.x;
        o.y = acc[i2][1] + bias.y;
        o.z = acc[i2][2] + bias.z;
        o.w = acc[i2][3] + bias.w;
        *(float4*)(g_xg + (((size_t)tt2 * NCTA + grp * GD + l) * 4 + bq) * 64 + c63) = o;
    }
}

// ---------------- Phase 2: persistent recurrence, sentinel data-poll sync ----------------
__device__ __forceinline__ float sig_(float v) {
    return __fdividef(1.f, 1.f + __expf(-v));
}
__device__ __forceinline__ float tanh_(float v) {
    return 1.f - __fdividef(2.f, 1.f + __expf(2.f * v));
}

__global__ __launch_bounds__(NTHR2, 1) void lstm_kernel(float* __restrict__ out, int out_size)
{
    __shared__ float xs[64][4];       // staged xg [col64][bq]
    __shared__ float z_s[16][4][4];   // [dimw][gate][bq]

    int cta  = blockIdx.x;
    int g    = cta >> 4;              // batch group
    int l    = cta & 15;              // dim slice
    int tid  = threadIdx.x;
    int lane = tid & 31;
    int w    = tid >> 5;              // warp -> local dim w, gate cols w*4..w*4+3

    // hoist U into registers (time-invariant), R8-proven layout
    unsigned long long u2[2][2][4];
#pragma unroll
    for (int iq = 0; iq < 2; ++iq)
#pragma unroll
        for (int pp = 0; pp < 2; ++pp)
#pragma unroll
            for (int cc = 0; cc < 4; ++cc) {
                int col = l * 64 + w * 4 + cc;
                int k   = (iq * 32 + lane) * 4 + pp * 2;
                unsigned lo = __float_as_uint(g_Up[(size_t)k * G4 + col]);
                unsigned hi = __float_as_uint(g_Up[(size_t)(k + 1) * G4 + col]);
                u2[iq][pp][cc] = ((unsigned long long)hi << 32) | lo;
            }

    int dimw = tid >> 2;              // gate threads (tid<64)
    int bq_g = tid & 3;
    float cstate = 0.f;

    // xg prefetch threads (tid<64): bq = tid>>4, col offset = (tid&15)*4
    int pbq = tid >> 4;
    int pc  = (tid & 15) * 4;
    float4 xv = make_float4(0.f, 0.f, 0.f, 0.f);
    if (tid < 64)
        xv = __ldg((const float4*)(g_xg + (((size_t)0 * NCTA + cta) * 4 + pbq) * 64 + pc));

    // poller assignment (tid<256): batch quad bq = tid>>6, quad index q = tid&63
    int pl_bq = tid >> 6;
    int pl_q  = tid & 63;

    __syncthreads();

    for (int t = 0; t < S; ++t) {
        // park this step's xg; issue next step's prefetch (overlaps the wait)
        if (tid < 64) {
            xs[pc + 0][pbq] = xv.x;
            xs[pc + 1][pbq] = xv.y;
            xs[pc + 2][pbq] = xv.z;
            xs[pc + 3][pbq] = xv.w;
            if (t + 1 < S)
                xv = __ldg((const float4*)(g_xg + (((size_t)(t + 1) * NCTA + cta) * 4 + pbq) * 64 + pc));
        }

        // wait for h_{t-1}: poll the DATA itself (one word per 16B quad;
        // STG.128 atomicity makes the whole quad valid once any word != SENT)
        const float* hs = g_hseq + (size_t)t * (B * H) + (size_t)(g * 4) * H;
        if (t > 0 && tid < 256) {
            const unsigned* wp = (const unsigned*)(hs + pl_bq * H + pl_q * 4);
            unsigned v;
            do {
                asm volatile("ld.volatile.global.b32 %0, [%1];" : "=r"(v) : "l"(wp));
            } while (v == SENT);
        }
        __syncthreads();

        // load h_{t-1} (plain LDG: fresh lines, never stale in L1)
        float4 hq[2][4];
#pragma unroll
        for (int iq = 0; iq < 2; ++iq)
#pragma unroll
            for (int bq = 0; bq < 4; ++bq)
                hq[iq][bq] = *(const float4*)(hs + bq * H + (iq * 32 + lane) * 4);

        unsigned long long acc[4][4];   // [cc][bq]
#pragma unroll
        for (int cc = 0; cc < 4; ++cc)
#pragma unroll
            for (int bq = 0; bq < 4; ++bq) acc[cc][bq] = 0ull;

#pragma unroll
        for (int iq = 0; iq < 2; ++iq)
#pragma unroll
            for (int bq = 0; bq < 4; ++bq) {
                unsigned long long hx =
                    ((unsigned long long)__float_as_uint(hq[iq][bq].y) << 32) | __float_as_uint(hq[iq][bq].x);
                unsigned long long hy =
                    ((unsigned long long)__float_as_uint(hq[iq][bq].w) << 32) | __float_as_uint(hq[iq][bq].z);
#pragma unroll
                for (int cc = 0; cc < 4; ++cc) {
                    asm("fma.rn.f32x2 %0, %1, %2, %0;"
                        : "+l"(acc[cc][bq]) : "l"(u2[iq][0][cc]), "l"(hx));
                    asm("fma.rn.f32x2 %0, %1, %2, %0;"
                        : "+l"(acc[cc][bq]) : "l"(u2[iq][1][cc]), "l"(hy));
                }
            }

        // horizontal pair add -> v[m], m = cc*4+bq
        float v[16];
#pragma unroll
        for (int cc = 0; cc < 4; ++cc)
#pragma unroll
            for (int bq = 0; bq < 4; ++bq) {
                unsigned long long a = acc[cc][bq];
                v[cc * 4 + bq] =
                    __uint_as_float((unsigned)a) + __uint_as_float((unsigned)(a >> 32));
            }

        // warp butterfly reduction over 32 lanes (k-slices), 16 outputs (R8-proven)
        {
            bool b4 = (lane & 16) != 0;
#pragma unroll
            for (int m = 0; m < 8; ++m) {
                float send = b4 ? v[m] : v[m + 8];
                float recv = __shfl_xor_sync(0xffffffffu, send, 16);
                v[m] = (b4 ? v[m + 8] : v[m]) + recv;
            }
            bool b3 = (lane & 8) != 0;
#pragma unroll
            for (int m = 0; m < 4; ++m) {
                float send = b3 ? v[m] : v[m + 4];
                float recv = __shfl_xor_sync(0xffffffffu, send, 8);
                v[m] = (b3 ? v[m + 4] : v[m]) + recv;
            }
            bool b2 = (lane & 4) != 0;
#pragma unroll
            for (int m = 0; m < 2; ++m) {
                float send = b2 ? v[m] : v[m + 2];
                float recv = __shfl_xor_sync(0xffffffffu, send, 4);
                v[m] = (b2 ? v[m + 2] : v[m]) + recv;
            }
            bool b1 = (lane & 2) != 0;
            {
                float send = b1 ? v[0] : v[1];
                float recv = __shfl_xor_sync(0xffffffffu, send, 2);
                v[0] = (b1 ? v[1] : v[0]) + recv;
            }
            v[0] += __shfl_xor_sync(0xffffffffu, v[0], 1);
        }
        if ((lane & 1) == 0) {
            int m = ((lane >> 4) & 1) * 8 + ((lane >> 3) & 1) * 4 +
                    ((lane >> 2) & 1) * 2 + ((lane >> 1) & 1);
            z_s[w][m >> 2][m & 3] = v[0];
        }
        __syncthreads();

        float hh = 0.f;
        if (tid < 64) {
            float zf = z_s[dimw][0][bq_g] + xs[dimw * 4 + 0][bq_g];
            float zi = z_s[dimw][1][bq_g] + xs[dimw * 4 + 1][bq_g];
            float zc = z_s[dimw][2][bq_g] + xs[dimw * 4 + 2][bq_g];
            float zo = z_s[dimw][3][bq_g] + xs[dimw * 4 + 3][bq_g];
            float f  = sig_(zf);
            float ii = sig_(zi);
            float gg = tanh_(zc);
            float oo = sig_(zo);
            cstate = fmaf(f, cstate, ii * gg);
            hh = oo * tanh_(cstate);

            // publish h_t via STG.128 quads: gather 4 dims of same batch via warp shuffles.
            // lane layout: tid = dimw*4 + bq; quad base lanes have (lane & 12) == 0.
            float v0 = hh;
            float v1 = __shfl_down_sync(0xffffffffu, hh, 4);
            float v2 = __shfl_down_sync(0xffffffffu, hh, 8);
            float v3 = __shfl_down_sync(0xffffffffu, hh, 12);
            if ((lane & 12) == 0) {
                int q    = lane >> 4;          // 0 or 1 within warp
                int dim0 = (tid >> 5) * 8 + q * 4;   // warp*8 + q*4
                int b    = lane & 3;
                float4 outq = make_float4(v0, v1, v2, v3);
                *(float4*)(g_hseq + (size_t)(t + 1) * (B * H) +
                           (size_t)(g * 4 + b) * H + l * 16 + dim0) = outq;
            }
        }

        // off-critical-path output stores
        if (tid < 64) {
            int b   = g * 4 + bq_g;
            int dim = l * 16 + dimw;
            out[(size_t)b * (S * H) + (size_t)t * H + dim] = hh;
            if (t == S - 1) {
                size_t base = (size_t)B * S * H;
                if ((size_t)out_size >= base + 2 * (size_t)B * H) {
                    out[base + (size_t)b * H + dim] = hh;
                    out[base + (size_t)B * H + (size_t)b * H + dim] = cstate;
                }
            }
        }
        __syncthreads();
    }
}

extern "C" void kernel_launch(void* const* d_in, const int* in_sizes, int n_in,
                              void* d_out, int out_size) {
    (void)in_sizes; (void)n_in;
    const float* x  = (const float*)d_in[0];
    const float* Wf = (const float*)d_in[1];
    const float* Uf = (const float*)d_in[2];
    const float* bf = (const float*)d_in[3];
    const float* Wi = (const float*)d_in[4];
    const float* Ui = (const float*)d_in[5];
    const float* bi = (const float*)d_in[6];
    const float* Wo = (const float*)d_in[7];
    const float* Uo = (const float*)d_in[8];
    const float* bo = (const float*)d_in[9];
    const float* Wc = (const float*)d_in[10];
    const float* Uc = (const float*)d_in[11];
    const float* bc = (const float*)d_in[12];

    pack_kernel<<<1024, 256>>>(Wf, Wi, Wc, Wo, Uf, Ui, Uc, Uo, bf, bi, bc, bo);
    hinit_kernel<<<4096, 256>>>();
    gemm_xg_kernel<<<dim3(G4 / BN, (S * B) / BM), 256>>>(x);
    lstm_kernel<<<NCTA, NTHR2>>>((float*)d_out, out_size);
}